// round 17
// baseline (speedup 1.0000x reference)
#include <cuda_runtime.h>
#include <cuda_bf16.h>
#include <cstdint>

// Problem constants (DenseKVMemory: B=1, M=32768, S=512, H=8, D=64)
#define M_   32768
#define S_   512
#define H_   8
#define D_   64
#define HD_  (H_ * D_)          // 512
#define CTX_ (M_ + S_)          // 33280

#define TN        32            // keys per tile
#define KSTK      68            // K smem row stride (conflict-free QK b-frags)
#define KSTV      72            // V smem row stride (conflict-free PV b-frags)
#define PST       36            // P^T smem stride (conflict-free st/ld)
#define NW        4             // warps per block
#define BQ        128           // queries per block (32 per warp)
#define NTHREADS  128
#define NSPLIT    9
#define NTILES    (CTX_ / TN)            // 1040
#define TSPL      116                    // tiles per split (last split gets 112)
#define NBUF      3                      // cp.async pipeline depth

#define NATTN     288           // CTAs (4 qtiles x 8 heads x 9 splits)

#define MBASE     8.0f          // fixed softmax base (softmax invariant to base)

// Inline copy: 2 float4 per tensor per thread per iter, 57 iters
#define CPW       14592
#define CPITERS   57
#define TOTAL4    ((M_ * HD_) / 4)             // 4194304

// dynamic smem layout (floats), 3 K/V buffers + 2 P parity buffers
#define K_OFF 0
#define V_OFF (NBUF * TN * KSTK)                   // 6528
#define P_OFF (V_OFF + NBUF * TN * KSTV)           // 13440
#define SMEM_FLOATS (P_OFF + 2 * NW * TN * PST)    // 22656
#define SMEM_BYTES  (SMEM_FLOATS * 4)              // 90624 -> exactly 2 CTAs/SM

#define KIDX(b,r,c)    (K_OFF + (b) * (TN * KSTK) + (r) * KSTK + (c))
#define VIDX(b,r,c)    (V_OFF + (b) * (TN * KSTV) + (r) * KSTV + (c))
#define PIDX(p,w,k,q)  (P_OFF + (p) * (NW * TN * PST) + (w) * (TN * PST) + (k) * PST + (q))

// Output layout: y | new_mem_keys | new_mem_vals | new_write_index
#define OFF_Y   0
#define OFF_MK  (S_ * HD_)                 // 262144
#define OFF_MV  (OFF_MK + M_ * HD_)        // 17039360
#define OFF_WI  (OFF_MV + M_ * HD_)        // 33816576

// Split-K partial scratch (device globals: no allocation allowed)
__device__ float g_pacc[NSPLIT][S_][H_][D_];
__device__ float g_pm[NSPLIT][S_][H_];
__device__ float g_pl[NSPLIT][S_][H_];

// ---------------- helpers ----------------
__device__ __forceinline__ uint32_t f2tf(float x) {
    uint32_t r;
    asm("cvt.rna.tf32.f32 %0, %1;" : "=r"(r) : "f"(x));
    return r;
}
__device__ __forceinline__ void mma8(float* d, const uint32_t* a, uint32_t b0, uint32_t b1) {
    asm volatile(
        "mma.sync.aligned.m16n8k8.row.col.f32.tf32.tf32.f32 "
        "{%0,%1,%2,%3}, {%4,%5,%6,%7}, {%8,%9}, {%0,%1,%2,%3};\n"
        : "+f"(d[0]), "+f"(d[1]), "+f"(d[2]), "+f"(d[3])
        : "r"(a[0]), "r"(a[1]), "r"(a[2]), "r"(a[3]), "r"(b0), "r"(b1));
}
__device__ __forceinline__ void cp_async16(void* sdst, const void* gsrc) {
    unsigned sa = (unsigned)__cvta_generic_to_shared(sdst);
    asm volatile("cp.async.cg.shared.global [%0], [%1], 16;" :: "r"(sa), "l"(gsrc));
}

// ---------------- fused: skewed-pipeline attention + inline clear-copy ----------------
__global__ void __launch_bounds__(NTHREADS)
fused_kernel(const float* __restrict__ memK, const float* __restrict__ memV,
             const float* __restrict__ segK, const float* __restrict__ segV,
             const float* __restrict__ Qg,
             float4* __restrict__ ok4, float4* __restrict__ ov4,
             const unsigned char* __restrict__ sos) {
    extern __shared__ __align__(16) float sm[];

    const int bid   = blockIdx.x;
    const float keepf = (sos != nullptr && sos[0]) ? 0.0f : 1.0f;

    const int tid   = threadIdx.x;
    const int w     = tid >> 5;
    const int lane  = tid & 31;
    const int g     = lane >> 2;
    const int l4    = lane & 3;
    const int xq    = bid & 3;
    const int h     = (bid >> 2) & 7;
    const int split = bid >> 5;
    const int q0    = xq * BQ;
    const int t0    = split * TSPL;
    const int tend  = (t0 + TSPL < NTILES) ? (t0 + TSPL) : NTILES;
    const int ntt   = tend - t0;               // 116 or 112

    const int qbase = q0 + w * 32;

    const float4* mk4 = (const float4*)memK;
    const float4* mv4 = (const float4*)memV;
    const int cpbase = bid * CPW;

    // ---- Q fragments in registers (pre-scaled, tf32-rounded): 2 m16 halves ----
    uint32_t qa[8][8];
    #pragma unroll
    for (int kc = 0; kc < 8; kc++) {
        #pragma unroll
        for (int hh = 0; hh < 2; hh++) {
            const int qr0 = qbase + hh * 16 + g;
            const int qr1 = qr0 + 8;
            const int d0 = kc * 8 + l4;
            qa[kc][hh * 4 + 0] = f2tf(Qg[(qr0 * H_ + h) * D_ + d0]     * 0.125f);
            qa[kc][hh * 4 + 1] = f2tf(Qg[(qr1 * H_ + h) * D_ + d0]     * 0.125f);
            qa[kc][hh * 4 + 2] = f2tf(Qg[(qr0 * H_ + h) * D_ + d0 + 4] * 0.125f);
            qa[kc][hh * 4 + 3] = f2tf(Qg[(qr1 * H_ + h) * D_ + d0 + 4] * 0.125f);
        }
    }

    // ---- async tile loader (reads ORIGINAL mem; keep applied to logits/P) ----
    const int lr  = tid >> 4;
    const int lch = (tid & 15) * 4;
    auto issue_tile = [&](int t, int buf) {
        const int c0 = t * TN;
        const bool mem = (c0 < M_);
        const float* Ksrc = mem ? memK : segK;
        const float* Vsrc = mem ? memV : segV;
        const int row0 = mem ? c0 : (c0 - M_);
        #pragma unroll
        for (int rep = 0; rep < 4; rep++) {
            const int row = lr + rep * 8;
            const long goff = (long)(row0 + row) * HD_ + h * D_ + lch;
            cp_async16(&sm[KIDX(buf, row, lch)], Ksrc + goff);
            cp_async16(&sm[VIDX(buf, row, lch)], Vsrc + goff);
        }
    };

    // per-thread partial l; O never rescaled (fixed base)
    float l[2][2];
    float o[2][8][4];
    #pragma unroll
    for (int hh = 0; hh < 2; hh++) {
        l[hh][0] = 0.0f; l[hh][1] = 0.0f;
        #pragma unroll
        for (int jn = 0; jn < 8; jn++)
            #pragma unroll
            for (int e = 0; e < 4; e++) o[hh][jn][e] = 0.0f;
    }

    // ---- stage A: QK + fixed-base softmax for global tile t -> P[par] ----
    auto qk_softmax = [&](int t, int buf, int par) {
        float s[2][4][4];
        #pragma unroll
        for (int hh = 0; hh < 2; hh++)
            #pragma unroll
            for (int jn = 0; jn < 4; jn++)
                #pragma unroll
                for (int e = 0; e < 4; e++) s[hh][jn][e] = 0.0f;

        #pragma unroll
        for (int kc = 0; kc < 8; kc++) {
            #pragma unroll
            for (int jn = 0; jn < 4; jn++) {
                const uint32_t b0 = __float_as_uint(sm[KIDX(buf, jn * 8 + g, kc * 8 + l4)]);
                const uint32_t b1 = __float_as_uint(sm[KIDX(buf, jn * 8 + g, kc * 8 + l4 + 4)]);
                mma8(s[0][jn], &qa[kc][0], b0, b1);
                mma8(s[1][jn], &qa[kc][4], b0, b1);
            }
        }

        const int kbase = t * TN;
        const bool is_mem = (kbase < M_);
        const float smul = is_mem ? keepf : 1.0f;

        if (is_mem) {
            #pragma unroll
            for (int hh = 0; hh < 2; hh++)
                #pragma unroll
                for (int jn = 0; jn < 4; jn++)
                    #pragma unroll
                    for (int e = 0; e < 4; e++) s[hh][jn][e] *= smul;
        } else {
            #pragma unroll
            for (int hh = 0; hh < 2; hh++) {
                const int qr0 = qbase + hh * 16 + g;
                const int qr1 = qr0 + 8;
                #pragma unroll
                for (int jn = 0; jn < 4; jn++) {
                    const int kg = kbase - M_ + jn * 8 + 2 * l4;
                    if (kg     >= qr0) s[hh][jn][0] = -1e30f;
                    if (kg + 1 >= qr0) s[hh][jn][1] = -1e30f;
                    if (kg     >= qr1) s[hh][jn][2] = -1e30f;
                    if (kg + 1 >= qr1) s[hh][jn][3] = -1e30f;
                }
            }
        }

        #pragma unroll
        for (int hh = 0; hh < 2; hh++) {
            float sum0 = 0.0f, sum1 = 0.0f;
            #pragma unroll
            for (int jn = 0; jn < 4; jn++) {
                const float p00 = __expf(s[hh][jn][0] - MBASE);
                const float p01 = __expf(s[hh][jn][1] - MBASE);
                const float p10 = __expf(s[hh][jn][2] - MBASE);
                const float p11 = __expf(s[hh][jn][3] - MBASE);
                sum0 += p00 + p01;
                sum1 += p10 + p11;
                const int kr = jn * 8 + 2 * l4;
                sm[PIDX(par, w, kr,     hh * 16 + g)]     = __uint_as_float(f2tf(p00 * smul));
                sm[PIDX(par, w, kr + 1, hh * 16 + g)]     = __uint_as_float(f2tf(p01 * smul));
                sm[PIDX(par, w, kr,     hh * 16 + 8 + g)] = __uint_as_float(f2tf(p10 * smul));
                sm[PIDX(par, w, kr + 1, hh * 16 + 8 + g)] = __uint_as_float(f2tf(p11 * smul));
            }
            l[hh][0] += sum0;
            l[hh][1] += sum1;
        }
    };

    // ---- stage B: O += P[par] @ V(buf) ----
    auto pv = [&](int buf, int par) {
        #pragma unroll
        for (int kc = 0; kc < 4; kc++) {
            uint32_t pa0[4], pa1[4];
            pa0[0] = __float_as_uint(sm[PIDX(par, w, kc * 8 + l4,     g)]);
            pa0[1] = __float_as_uint(sm[PIDX(par, w, kc * 8 + l4,     8 + g)]);
            pa0[2] = __float_as_uint(sm[PIDX(par, w, kc * 8 + l4 + 4, g)]);
            pa0[3] = __float_as_uint(sm[PIDX(par, w, kc * 8 + l4 + 4, 8 + g)]);
            pa1[0] = __float_as_uint(sm[PIDX(par, w, kc * 8 + l4,     16 + g)]);
            pa1[1] = __float_as_uint(sm[PIDX(par, w, kc * 8 + l4,     24 + g)]);
            pa1[2] = __float_as_uint(sm[PIDX(par, w, kc * 8 + l4 + 4, 16 + g)]);
            pa1[3] = __float_as_uint(sm[PIDX(par, w, kc * 8 + l4 + 4, 24 + g)]);
            #pragma unroll
            for (int jn = 0; jn < 8; jn++) {
                const uint32_t b0 = __float_as_uint(sm[VIDX(buf, kc * 8 + l4,     jn * 8 + g)]);
                const uint32_t b1 = __float_as_uint(sm[VIDX(buf, kc * 8 + l4 + 4, jn * 8 + g)]);
                mma8(o[0][jn], pa0, b0, b1);
                mma8(o[1][jn], pa1, b0, b1);
            }
        }
    };

    // ---- prologue: tiles t0, t0+1 in flight; QK(t0) done before loop ----
    issue_tile(t0, 0);
    asm volatile("cp.async.commit_group;" ::: "memory");
    issue_tile(t0 + 1, 1);   // ntt >= 112, always valid
    asm volatile("cp.async.commit_group;" ::: "memory");
    asm volatile("cp.async.wait_group 1;" ::: "memory");   // tile t0 arrived
    __syncthreads();
    qk_softmax(t0, 0, 0);    // P[0] = P(t0)

    // ---- skewed mainloop: iter tt does QK(tt+1) and PV(tt) ----
    for (int tt = 0; tt < ntt; tt++) {
        const int buf = tt % NBUF;
        if (tt + 2 < ntt) issue_tile(t0 + tt + 2, (tt + 2) % NBUF);
        asm volatile("cp.async.commit_group;" ::: "memory");

        // inline copy: issue loads early
        float4 ca0, cb0, ca1, cb1;
        const int cidx0 = cpbase + tt * 256 + tid;
        const int cidx1 = cidx0 + 128;
        const bool docp = (tt < CPITERS);
        if (docp) {
            if (cidx0 < TOTAL4) { ca0 = mk4[cidx0]; cb0 = mv4[cidx0]; }
            if (cidx1 < TOTAL4) { ca1 = mk4[cidx1]; cb1 = mv4[cidx1]; }
        }

        asm volatile("cp.async.wait_group 1;" ::: "memory");   // tile tt+1 arrived
        __syncthreads();

        // QK+softmax of tile tt+1 (independent of PV below; scheduler interleaves)
        if (tt + 1 < ntt) qk_softmax(t0 + tt + 1, (tt + 1) % NBUF, (tt + 1) & 1);

        // PV of tile tt from P[tt&1] (written last iteration, fenced by the barrier)
        pv(buf, tt & 1);

        // inline copy: drain
        if (docp) {
            if (cidx0 < TOTAL4) {
                ca0.x *= keepf; ca0.y *= keepf; ca0.z *= keepf; ca0.w *= keepf;
                cb0.x *= keepf; cb0.y *= keepf; cb0.z *= keepf; cb0.w *= keepf;
                ok4[cidx0] = ca0;
                ov4[cidx0] = cb0;
            }
            if (cidx1 < TOTAL4) {
                ca1.x *= keepf; ca1.y *= keepf; ca1.z *= keepf; ca1.w *= keepf;
                cb1.x *= keepf; cb1.y *= keepf; cb1.z *= keepf; cb1.w *= keepf;
                ok4[cidx1] = ca1;
                ov4[cidx1] = cb1;
            }
        }

        __syncthreads();   // all warps done with buf (K of tt+1, V of tt, P parities)
    }

    // ---- final l reduction across the 4-lane quad, then write split partials ----
    #pragma unroll
    for (int hh = 0; hh < 2; hh++) {
        l[hh][0] += __shfl_xor_sync(0xffffffffu, l[hh][0], 1);
        l[hh][0] += __shfl_xor_sync(0xffffffffu, l[hh][0], 2);
        l[hh][1] += __shfl_xor_sync(0xffffffffu, l[hh][1], 1);
        l[hh][1] += __shfl_xor_sync(0xffffffffu, l[hh][1], 2);
    }

    #pragma unroll
    for (int hh = 0; hh < 2; hh++) {
        const int qr0 = qbase + hh * 16 + g;
        const int qr1 = qr0 + 8;
        #pragma unroll
        for (int jn = 0; jn < 8; jn++) {
            const int d = jn * 8 + 2 * l4;
            *(float2*)&g_pacc[split][qr0][h][d] = make_float2(o[hh][jn][0], o[hh][jn][1]);
            *(float2*)&g_pacc[split][qr1][h][d] = make_float2(o[hh][jn][2], o[hh][jn][3]);
        }
        if (l4 == 0) {
            g_pm[split][qr0][h] = MBASE; g_pl[split][qr0][h] = l[hh][0];
            g_pm[split][qr1][h] = MBASE; g_pl[split][qr1][h] = l[hh][1];
        }
    }
}

// ---------------- epilogue: split-K combine + scatter + write_index ----------------
__global__ void epilogue_kernel(float* __restrict__ Y,
                                const float4* __restrict__ k4, const float4* __restrict__ v4,
                                float4* __restrict__ ok, float4* __restrict__ ov,
                                const int* __restrict__ wip, float* __restrict__ out_wi) {
    const int i = blockIdx.x * blockDim.x + threadIdx.x;

    if (i < S_ * H_ * D_) {
        const int q = i / (H_ * D_);
        const int hd = i % (H_ * D_);
        const int h = hd / D_;
        const int d = hd % D_;
        float m = -1e30f;
        #pragma unroll
        for (int s = 0; s < NSPLIT; s++) m = fmaxf(m, g_pm[s][q][h]);
        float lsum = 0.0f, asum = 0.0f;
        #pragma unroll
        for (int s = 0; s < NSPLIT; s++) {
            const float wgt = __expf(g_pm[s][q][h] - m);
            lsum += g_pl[s][q][h] * wgt;
            asum += g_pacc[s][q][h][d] * wgt;
        }
        Y[i] = asum / lsum;
    }

    if (i < (S_ * HD_) / 4) {
        int wi = wip ? *wip : 0;
        int wic = wi < 0 ? 0 : (wi > (M_ - S_) ? (M_ - S_) : wi);
        const int base = wic * (HD_ / 4);
        ok[base + i] = k4[i];
        ov[base + i] = v4[i];
    }

    if (i == 0) {
        int wi = wip ? *wip : 0;
        out_wi[0] = (float)((wi + S_) % M_);
    }
}

extern "C" void kernel_launch(void* const* d_in, const int* in_sizes, int n_in,
                              void* d_out, int out_size) {
    const float* mk = (const float*)d_in[0];
    const float* mv = (const float*)d_in[1];
    const float* ks = (const float*)d_in[2];
    const float* vs = (const float*)d_in[3];
    const float* qs = (const float*)d_in[4];
    const unsigned char* sos = (n_in > 5) ? (const unsigned char*)d_in[5] : nullptr;
    const int* wip = (n_in > 6) ? (const int*)d_in[6] : nullptr;

    float* out = (float*)d_out;
    float* y  = out + OFF_Y;
    float* ok = out + OFF_MK;
    float* ov = out + OFF_MV;

    cudaFuncSetAttribute(fused_kernel, cudaFuncAttributeMaxDynamicSharedMemorySize, SMEM_BYTES);

    fused_kernel<<<NATTN, NTHREADS, SMEM_BYTES>>>(mk, mv, ks, vs, qs,
                                                  (float4*)ok, (float4*)ov, sos);

    epilogue_kernel<<<(S_ * H_ * D_ + 255) / 256, 256>>>(
        y, (const float4*)ks, (const float4*)vs, (float4*)ok, (float4*)ov,
        wip, (out_size > OFF_WI) ? (out + OFF_WI) : nullptr);
}